// round 8
// baseline (speedup 1.0000x reference)
#include <cuda_runtime.h>
#include <math.h>
#include <stdint.h>

#define NA 20000
#define NE 640000
#define DD 128
#define GG 32
#define HH 8
#define NIT 4
#define NSM 148

// ---------------- device scratch ----------------
__device__ float    g_Wfil[(size_t)NE * DD];
__device__ int      g_ssrc[NE];     // src, sorted by dst
__device__ int      g_sdst[NE];
__device__ int      g_lsrc[NE];     // live subset, sorted by dst
__device__ int      g_lpos[NE];
__device__ int      g_ldst[NE];
__device__ int      g_cnt_all[NA];  // statically zero; re-zeroed by final k_out
__device__ int      g_cnt_live[NA];
__device__ int      g_off_all[NA];
__device__ int      g_off_live[NA];
__device__ int      g_nlive;
__device__ float    g_h[NA * DD];
__device__ float    g_Q[NA * DD];
__device__ float    g_K[NA * DD];
__device__ float    g_s[NE * HH];
__device__ float    g_msg[NA * DD];

__device__ __forceinline__ void red_add_v2(float* p, float x, float y) {
    asm volatile("red.global.add.v2.f32 [%0], {%1,%2};"
                 :: "l"(p), "f"(x), "f"(y) : "memory");
}
__device__ __forceinline__ float edge_r(const float* xyz, int s, int d) {
    float dx = xyz[3 * s]     - xyz[3 * d];
    float dy = xyz[3 * s + 1] - xyz[3 * d + 1];
    float dz = xyz[3 * s + 2] - xyz[3 * d + 2];
    return sqrtf(dx * dx + dy * dy + dz * dz + 1e-12f);
}

// ---------------- tf32 MMA core with fragment-major smem ----------------
__device__ __forceinline__ uint32_t f2tf(float f) {
    uint32_t u;
    asm("cvt.rna.tf32.f32 %0, %1;" : "=r"(u) : "f"(f));
    return u;
}
__device__ __forceinline__ float f2tff(float f) { return __uint_as_float(f2tf(f)); }

__device__ __forceinline__ void mma8(float4& d,
                                     uint32_t a0, uint32_t a1, uint32_t a2, uint32_t a3,
                                     uint32_t b0, uint32_t b1) {
    asm volatile(
        "mma.sync.aligned.m16n8k8.row.col.f32.tf32.tf32.f32 "
        "{%0,%1,%2,%3},{%4,%5,%6,%7},{%8,%9},{%0,%1,%2,%3};"
        : "+f"(d.x), "+f"(d.y), "+f"(d.z), "+f"(d.w)
        : "r"(a0), "r"(a1), "r"(a2), "r"(a3), "r"(b0), "r"(b1));
}
template <int KB>
__device__ __forceinline__ int fragA_idx(int r, int k) {
    return (((r >> 4) * KB + (k >> 3)) << 7) + (((r & 7) * 4 + (k & 3)) << 2)
         + ((r >> 3) & 1) + (((k >> 2) & 1) << 1);
}
template <int KB>
__device__ __forceinline__ int fragB_idx(int k, int n) {
    return (((n >> 4) * KB + (k >> 3)) << 7) + (((n & 7) * 4 + (k & 3)) << 2)
         + (((n >> 3) & 1) << 1) + ((k >> 2) & 1);
}
#define FAU(x) __float_as_uint(x)
template <int KB>
__device__ __forceinline__ void mma_tile_frag(const float* __restrict__ sA,
                                              const float* __restrict__ sB,
                                              int wm, int wn, int lane,
                                              float4 acc[2][4]) {
    const float4* A = (const float4*)sA;
    const float4* B = (const float4*)sB;
#pragma unroll
    for (int kk = 0; kk < KB; kk++) {
        float4 a0 = A[((2 * wm)     * KB + kk) * 32 + lane];
        float4 a1 = A[((2 * wm + 1) * KB + kk) * 32 + lane];
        float4 b0 = B[((2 * wn)     * KB + kk) * 32 + lane];
        float4 b1 = B[((2 * wn + 1) * KB + kk) * 32 + lane];
        mma8(acc[0][0], FAU(a0.x), FAU(a0.y), FAU(a0.z), FAU(a0.w), FAU(b0.x), FAU(b0.y));
        mma8(acc[1][0], FAU(a1.x), FAU(a1.y), FAU(a1.z), FAU(a1.w), FAU(b0.x), FAU(b0.y));
        mma8(acc[0][1], FAU(a0.x), FAU(a0.y), FAU(a0.z), FAU(a0.w), FAU(b0.z), FAU(b0.w));
        mma8(acc[1][1], FAU(a1.x), FAU(a1.y), FAU(a1.z), FAU(a1.w), FAU(b0.z), FAU(b0.w));
        mma8(acc[0][2], FAU(a0.x), FAU(a0.y), FAU(a0.z), FAU(a0.w), FAU(b1.x), FAU(b1.y));
        mma8(acc[1][2], FAU(a1.x), FAU(a1.y), FAU(a1.z), FAU(a1.w), FAU(b1.x), FAU(b1.y));
        mma8(acc[0][3], FAU(a0.x), FAU(a0.y), FAU(a0.z), FAU(a0.w), FAU(b1.z), FAU(b1.w));
        mma8(acc[1][3], FAU(a1.x), FAU(a1.y), FAU(a1.z), FAU(a1.w), FAU(b1.z), FAU(b1.w));
    }
}
__device__ __forceinline__ void zacc4(float4 acc[2][4]) {
#pragma unroll
    for (int i = 0; i < 2; i++)
#pragma unroll
        for (int j = 0; j < 4; j++) acc[i][j] = make_float4(0.f, 0.f, 0.f, 0.f);
}

// ---------------- setup ----------------
__global__ void k_hist(const float* __restrict__ xyz, const int* __restrict__ src,
                       const int* __restrict__ dst) {
    int e = blockIdx.x * blockDim.x + threadIdx.x;
    if (e >= NE) return;
    int s = src[e], d = dst[e];
    atomicAdd(&g_cnt_all[d], 1);
    if (edge_r(xyz, s, d) < 8.f) atomicAdd(&g_cnt_live[d], 1);
}

__global__ __launch_bounds__(512) void k_scan() {
    __shared__ int part[512];
    __shared__ int total;
    int t = threadIdx.x;
    const int CH = (NA + 511) / 512;
#pragma unroll 1
    for (int pass = 0; pass < 2; pass++) {
        int* cnt = pass ? g_cnt_live : g_cnt_all;
        int* off = pass ? g_off_live : g_off_all;
        int lo = t * CH, hi = min(lo + CH, NA);
        int s = 0;
        for (int i = lo; i < hi; i++) s += cnt[i];
        part[t] = s;
        __syncthreads();
        if (t == 0) {
            int run = 0;
            for (int i = 0; i < 512; i++) { int v = part[i]; part[i] = run; run += v; }
            total = run;
        }
        __syncthreads();
        int run = part[t];
        for (int i = lo; i < hi; i++) { int v = cnt[i]; off[i] = run; run += v; cnt[i] = 0; }
        if (pass == 1 && t == 0) g_nlive = total;
        __syncthreads();
    }
}

__global__ void k_scatter(const float* __restrict__ xyz, const int* __restrict__ src,
                          const int* __restrict__ dst) {
    int e = blockIdx.x * blockDim.x + threadIdx.x;
    if (e >= NE) return;
    int s = src[e], d = dst[e];
    int pos = g_off_all[d] + atomicAdd(&g_cnt_all[d], 1);
    g_ssrc[pos] = s;
    g_sdst[pos] = d;
    if (edge_r(xyz, s, d) < 8.f) {
        int lp = g_off_live[d] + atomicAdd(&g_cnt_live[d], 1);
        g_lsrc[lp] = s; g_ldst[lp] = d; g_lpos[lp] = pos;
    }
}

__global__ void k_embed(const float* __restrict__ emb, const int* __restrict__ z,
                        float* __restrict__ x) {
    int i = blockIdx.x * blockDim.x + threadIdx.x;
    if (i < NA * DD) {
        int n = i >> 7, d = i & 127;
        x[i] = emb[z[n] * DD + d];
    }
}

// ---------------- filter (persistent, tf32, fragment smem) ----------------
__global__ __launch_bounds__(512) void k_filter(
    const float* __restrict__ xyz,
    const float* __restrict__ Wl, const float* __restrict__ bl,
    const float* __restrict__ W1f, const float* __restrict__ b1f,
    const float* __restrict__ W2f, const float* __restrict__ b2f) {
    extern __shared__ float sm[];
    float* sf   = sm;
    float* sg   = sf + 4096;
    float* sW1t = sg + 16384;
    float* sWlt = sW1t + 4096;
    float* sW2t = sWlt + 4096;
    float* sr   = sW2t + 16384;
    float* sC   = sr + 128;
    float* sb1  = sC + 128;
    float* sb   = sb1 + 128;

    int tid = threadIdx.x, lane = tid & 31, w = tid >> 5;
    int wm = w & 3, wn = w >> 2;
    int g = lane >> 2, t4 = lane & 3;

    for (int i = tid; i < 32 * 128; i += 512) {
        int k = i >> 7, n = i & 127;
        sW1t[fragB_idx<4>(k, n)] = f2tff(W1f[i]);
        sWlt[fragB_idx<4>(k, n)] = f2tff(Wl[i]);
    }
    for (int i = tid; i < 128 * 128; i += 512) {
        int k = i >> 7, n = i & 127;
        sW2t[fragB_idx<16>(k, n)] = f2tff(W2f[i]);
    }
    if (tid < 128) { sb1[tid] = b1f[tid]; sb[tid] = bl[tid] + b2f[tid]; }

    int nlive = g_nlive;
    for (int tt = blockIdx.x; tt * 128 < nlive; tt += gridDim.x) {
        if (tid < 128) {
            int li = tt * 128 + tid;
            float r = 100.f, C = 0.f;
            if (li < nlive) {
                r = edge_r(xyz, g_lsrc[li], g_ldst[li]);
                C = (r < 8.f) ? (0.5f * (cospif(r * 0.125f) + 1.f)) : 0.f;
            }
            sr[tid] = r; sC[tid] = C;
        }
        __syncthreads();
        {
            int el = tid >> 2, kb = (tid & 3) * 8;
            float r = sr[el];
#pragma unroll
            for (int q = 0; q < 8; q++) {
                int k = kb + q;
                float off = (float)k * (8.f / 31.f);
                float u = (r - off) * (31.f / 8.f);
                sf[fragA_idx<4>(el, k)] = f2tff(__expf(-0.5f * u * u));
            }
        }
        __syncthreads();

        float4 acc[2][4];
        zacc4(acc);
        mma_tile_frag<4>(sf, sW1t, wm, wn, lane, acc);
        __syncthreads();
#pragma unroll
        for (int mi = 0; mi < 2; mi++) {
            int r = 32 * wm + 16 * mi + g;
#pragma unroll
            for (int jl = 0; jl < 4; jl++) {
                int c = 32 * wn + 8 * jl + 2 * t4;
                float4 d = acc[mi][jl];
                float v0 = d.x + sb1[c], v1 = d.y + sb1[c + 1];
                float v2 = d.z + sb1[c], v3 = d.w + sb1[c + 1];
                sg[fragA_idx<16>(r, c)]         = f2tff(v0 / (1.f + __expf(-v0)));
                sg[fragA_idx<16>(r, c + 1)]     = f2tff(v1 / (1.f + __expf(-v1)));
                sg[fragA_idx<16>(r + 8, c)]     = f2tff(v2 / (1.f + __expf(-v2)));
                sg[fragA_idx<16>(r + 8, c + 1)] = f2tff(v3 / (1.f + __expf(-v3)));
            }
        }
        __syncthreads();

        zacc4(acc);
        mma_tile_frag<4>(sf, sWlt, wm, wn, lane, acc);
        mma_tile_frag<16>(sg, sW2t, wm, wn, lane, acc);

#pragma unroll
        for (int mi = 0; mi < 2; mi++) {
            int r = 32 * wm + 16 * mi + g;
#pragma unroll
            for (int jl = 0; jl < 4; jl++) {
                int c = 32 * wn + 8 * jl + 2 * t4;
                float4 d = acc[mi][jl];
                int li0 = tt * 128 + r, li1 = li0 + 8;
                if (li0 < nlive) {
                    float Cv = sC[r];
                    *(float2*)(g_Wfil + (size_t)li0 * 128 + c) =
                        make_float2((d.x + sb[c]) * Cv, (d.y + sb[c + 1]) * Cv);
                }
                if (li1 < nlive) {
                    float Cv = sC[r + 8];
                    *(float2*)(g_Wfil + (size_t)li1 * 128 + c) =
                        make_float2((d.z + sb[c]) * Cv, (d.w + sb[c + 1]) * Cv);
                }
            }
        }
        __syncthreads();
    }
}

// ---------------- fused out+hqk: x += msg@Wo; h = x+te; Q = h@Wq; K = h@Wk ----------------
__global__ __launch_bounds__(512) void k_oqk(float* __restrict__ x,
                                             const float* __restrict__ te,
                                             const float* __restrict__ Wo,
                                             const float* __restrict__ Wq,
                                             const float* __restrict__ Wk, int it) {
    extern __shared__ float sm[];
    float* sA = sm;
    float* sB = sm + 16384;
    int tid = threadIdx.x, lane = tid & 31, w = tid >> 5;
    int wm = w & 3, wn = w >> 2;
    int g = lane >> 2, t4 = lane & 3;
    int n0 = blockIdx.x * 128;

    float4 acc[2][4];
    zacc4(acc);
    if (it > 0) {
        for (int i = tid; i < 128 * 128; i += 512) {
            int r = i >> 7, c = i & 127, n = n0 + r;
            sA[fragA_idx<16>(r, c)] = (n < NA) ? f2tff(g_msg[(size_t)n * 128 + c]) : 0.f;
        }
        for (int i = tid; i < 128 * 128; i += 512) {
            int k = i >> 7, n = i & 127;
            sB[fragB_idx<16>(k, n)] = f2tff(Wo[i]);
        }
        __syncthreads();
        mma_tile_frag<16>(sA, sB, wm, wn, lane, acc);
        __syncthreads();
    }
#pragma unroll
    for (int mi = 0; mi < 2; mi++) {
        int r = 32 * wm + 16 * mi + g;
#pragma unroll
        for (int jl = 0; jl < 4; jl++) {
            int c = 32 * wn + 8 * jl + 2 * t4;
            float4 d = acc[mi][jl];
            float te0 = te[it * 128 + c], te1 = te[it * 128 + c + 1];
            int n1 = n0 + r, n2 = n1 + 8;
            float h00 = 0.f, h01 = 0.f, h10 = 0.f, h11 = 0.f;
            if (n1 < NA) {
                float2 xv = *(float2*)(x + (size_t)n1 * 128 + c);
                xv.x += d.x; xv.y += d.y;
                *(float2*)(x + (size_t)n1 * 128 + c) = xv;
                h00 = xv.x + te0; h01 = xv.y + te1;
                *(float2*)(g_h + (size_t)n1 * 128 + c) = make_float2(h00, h01);
            }
            if (n2 < NA) {
                float2 xv = *(float2*)(x + (size_t)n2 * 128 + c);
                xv.x += d.z; xv.y += d.w;
                *(float2*)(x + (size_t)n2 * 128 + c) = xv;
                h10 = xv.x + te0; h11 = xv.y + te1;
                *(float2*)(g_h + (size_t)n2 * 128 + c) = make_float2(h10, h11);
            }
            sA[fragA_idx<16>(r, c)]         = f2tff(h00);
            sA[fragA_idx<16>(r, c + 1)]     = f2tff(h01);
            sA[fragA_idx<16>(r + 8, c)]     = f2tff(h10);
            sA[fragA_idx<16>(r + 8, c + 1)] = f2tff(h11);
        }
    }
    for (int i = tid; i < 128 * 128; i += 512) {
        int k = i >> 7, n = i & 127;
        sB[fragB_idx<16>(k, n)] = f2tff(Wq[i]);
    }
    __syncthreads();
    zacc4(acc);
    mma_tile_frag<16>(sA, sB, wm, wn, lane, acc);
#pragma unroll
    for (int mi = 0; mi < 2; mi++) {
        int r = 32 * wm + 16 * mi + g;
#pragma unroll
        for (int jl = 0; jl < 4; jl++) {
            int c = 32 * wn + 8 * jl + 2 * t4;
            float4 d = acc[mi][jl];
            int n1 = n0 + r, n2 = n1 + 8;
            if (n1 < NA) *(float2*)(g_Q + (size_t)n1 * 128 + c) = make_float2(d.x, d.y);
            if (n2 < NA) *(float2*)(g_Q + (size_t)n2 * 128 + c) = make_float2(d.z, d.w);
        }
    }
    __syncthreads();
    for (int i = tid; i < 128 * 128; i += 512) {
        int k = i >> 7, n = i & 127;
        sB[fragB_idx<16>(k, n)] = f2tff(Wk[i]);
    }
    __syncthreads();
    zacc4(acc);
    mma_tile_frag<16>(sA, sB, wm, wn, lane, acc);
#pragma unroll
    for (int mi = 0; mi < 2; mi++) {
        int r = 32 * wm + 16 * mi + g;
#pragma unroll
        for (int jl = 0; jl < 4; jl++) {
            int c = 32 * wn + 8 * jl + 2 * t4;
            float4 d = acc[mi][jl];
            int n1 = n0 + r, n2 = n1 + 8;
            if (n1 < NA) *(float2*)(g_K + (size_t)n1 * 128 + c) = make_float2(d.x, d.y);
            if (n2 < NA) *(float2*)(g_K + (size_t)n2 * 128 + c) = make_float2(d.z, d.w);
        }
    }
}

// ---------------- fused per-atom softmax: scores -> a, zero msg ----------------
__global__ __launch_bounds__(256) void k_soft() {
    int warp = (blockIdx.x * blockDim.x + threadIdx.x) >> 5;
    int lane = threadIdx.x & 31;
    if (warp >= NA) return;
    int d = warp;
    *(float4*)(g_msg + (size_t)d * 128 + lane * 4) = make_float4(0.f, 0.f, 0.f, 0.f);
    int beg = g_off_all[d], cnt = g_cnt_all[d];
    if (cnt == 0) return;

    float4 q = *(const float4*)(g_Q + (size_t)d * 128 + lane * 4);
    float m = -1e30f;
    for (int i = 0; i < cnt; i++) {
        int e = beg + i;
        int s = g_ssrc[e];
        float4 kv = *(const float4*)(g_K + (size_t)s * 128 + lane * 4);
        float p = q.x * kv.x + q.y * kv.y + q.z * kv.z + q.w * kv.w;
        p += __shfl_xor_sync(0xffffffffu, p, 1);
        p += __shfl_xor_sync(0xffffffffu, p, 2);
        p *= 0.25f;
        m = fmaxf(m, p);
        float t = __shfl_sync(0xffffffffu, p, (lane & 7) * 4);
        if (lane < 8) g_s[(size_t)e * 8 + lane] = t;
    }
    float mh = __shfl_sync(0xffffffffu, m, (lane & 7) * 4);
    int h = lane & 7, eo = lane >> 3;
    float den = 0.f;
    for (int base = 0; base < cnt; base += 4) {
        int i = base + eo;
        if (i < cnt) den += __expf(g_s[(size_t)(beg + i) * 8 + h] - mh);
    }
    den += __shfl_xor_sync(0xffffffffu, den, 8);
    den += __shfl_xor_sync(0xffffffffu, den, 16);
    float inv = 1.f / (den + 1e-12f);
    for (int base = 0; base < cnt; base += 4) {
        int i = base + eo;
        if (i < cnt) {
            size_t o = (size_t)(beg + i) * 8 + h;
            g_s[o] = __expf(g_s[o] - mh) * inv;
        }
    }
}

// ---------------- msgv: pipelined tf32 MMA + in-register segmented reduce ----------------
__global__ __launch_bounds__(512) void k_msgv(const float* __restrict__ Wv) {
    extern __shared__ float sm[];
    float* sA0  = sm;                    // frag A buf0 16384
    float* sA1  = sm + 16384;            // frag A buf1 16384
    float* sBt  = sm + 32768;            // frag B 16384
    float* sAf  = sm + 49152;            // 2 x 128*8
    int*   sDst = (int*)(sm + 51200);    // 2 x 128
    int tid = threadIdx.x, lane = tid & 31, w = tid >> 5;
    int wm = w & 3, wn = w >> 2;
    int g = lane >> 2, t4 = lane & 3;

    for (int i = tid; i < 128 * 128; i += 512) {
        int k = i >> 7, n = i & 127;
        sBt[fragB_idx<16>(k, n)] = f2tff(Wv[i]);
    }
    int nlive = g_nlive;
    int nt = (nlive + 127) >> 7;

    int r = tid >> 2, cb = (tid & 3) * 32;
    float v[32];
    float4 aw0 = make_float4(0.f, 0.f, 0.f, 0.f), aw1 = aw0;
    int dv = -1;

    // prefetch tile tt -> registers
    auto prefetch = [&](int tt) {
        int li = tt * 128 + r;
        if (li < nlive) {
            int s = g_lsrc[li];
            const float4* wf = (const float4*)(g_Wfil + (size_t)li * 128 + cb);
            const float4* hp = (const float4*)(g_h + (size_t)s * 128 + cb);
#pragma unroll
            for (int q = 0; q < 8; q++) {
                float4 ww = wf[q], hh = hp[q];
                v[4*q]   = ww.x * hh.x; v[4*q+1] = ww.y * hh.y;
                v[4*q+2] = ww.z * hh.z; v[4*q+3] = ww.w * hh.w;
            }
        } else {
#pragma unroll
            for (int q = 0; q < 32; q++) v[q] = 0.f;
        }
        if (tid < 128) {
            int li2 = tt * 128 + tid;
            if (li2 < nlive) {
                dv = g_ldst[li2];
                int pos = g_lpos[li2];
                aw0 = *(const float4*)(g_s + (size_t)pos * 8);
                aw1 = *(const float4*)(g_s + (size_t)pos * 8 + 4);
            } else {
                dv = -1;
                aw0 = make_float4(0.f, 0.f, 0.f, 0.f); aw1 = aw0;
            }
        }
    };
    auto stage = [&](float* sA, float* af, int* db) {
#pragma unroll
        for (int q = 0; q < 8; q++) {
            int i0 = fragA_idx<16>(r, cb + q * 4);
            sA[i0]      = f2tff(v[4*q]);
            sA[i0 + 4]  = f2tff(v[4*q+1]);
            sA[i0 + 8]  = f2tff(v[4*q+2]);
            sA[i0 + 12] = f2tff(v[4*q+3]);
        }
        if (tid < 128) {
            db[tid] = dv;
            *(float4*)(af + tid * 8)     = aw0;
            *(float4*)(af + tid * 8 + 4) = aw1;
        }
    };

    if (blockIdx.x < nt) { prefetch(blockIdx.x); stage(sA0, sAf, sDst); }
    __syncthreads();

    int cur = 0;
    for (int tt = blockIdx.x; tt < nt; tt += gridDim.x) {
        int ttn = tt + gridDim.x;
        bool hn = ttn < nt;
        if (hn) prefetch(ttn);   // global loads in flight during MMA

        float* sA = cur ? sA1 : sA0;
        const float* af = sAf + cur * 1024;
        const int* db = sDst + cur * 128;

        float4 acc[2][4];
        zacc4(acc);
        mma_tile_frag<16>(sA, sBt, wm, wn, lane, acc);

        // in-register epilogue: a ⊙ v, then dst-segmented reduce over the 8 g-rows
#pragma unroll
        for (int mi = 0; mi < 2; mi++) {
            int rr = 32 * wm + 16 * mi + g;
            int dA = db[rr], dB = db[rr + 8];
            int odA1 = __shfl_down_sync(0xffffffffu, dA, 4);
            int odB1 = __shfl_down_sync(0xffffffffu, dB, 4);
            int odA2 = __shfl_down_sync(0xffffffffu, dA, 8);
            int odB2 = __shfl_down_sync(0xffffffffu, dB, 8);
            int odA4 = __shfl_down_sync(0xffffffffu, dA, 16);
            int odB4 = __shfl_down_sync(0xffffffffu, dB, 16);
            bool eA1 = (g + 1 < 8) && (odA1 == dA);
            bool eB1 = (g + 1 < 8) && (odB1 == dB);
            bool eA2 = (g + 2 < 8) && (odA2 == dA);
            bool eB2 = (g + 2 < 8) && (odB2 == dB);
            bool eA4 = (g + 4 < 8) && (odA4 == dA);
            bool eB4 = (g + 4 < 8) && (odB4 == dB);
            int pdA = __shfl_up_sync(0xffffffffu, dA, 4);
            int pdB = __shfl_up_sync(0xffffffffu, dB, 4);
            bool headA = (dA >= 0) && (g == 0 || pdA != dA);
            bool headB = (dB >= 0) && (g == 0 || pdB != dB);
#pragma unroll
            for (int jl = 0; jl < 4; jl++) {
                int c = 32 * wn + 8 * jl + 2 * t4;
                int head = c >> 4;
                float aA = af[rr * 8 + head];
                float aB = af[(rr + 8) * 8 + head];
                float4 vv = acc[mi][jl];
                vv.x *= aA; vv.y *= aA; vv.z *= aB; vv.w *= aB;
                float ox, oy, oz, ow;
                ox = __shfl_down_sync(0xffffffffu, vv.x, 4);
                oy = __shfl_down_sync(0xffffffffu, vv.y, 4);
                oz = __shfl_down_sync(0xffffffffu, vv.z, 4);
                ow = __shfl_down_sync(0xffffffffu, vv.w, 4);
                if (eA1) { vv.x += ox; vv.y += oy; }
                if (eB1) { vv.z += oz; vv.w += ow; }
                ox = __shfl_down_sync(0xffffffffu, vv.x, 8);
                oy = __shfl_down_sync(0xffffffffu, vv.y, 8);
                oz = __shfl_down_sync(0xffffffffu, vv.z, 8);
                ow = __shfl_down_sync(0xffffffffu, vv.w, 8);
                if (eA2) { vv.x += ox; vv.y += oy; }
                if (eB2) { vv.z += oz; vv.w += ow; }
                ox = __shfl_down_sync(0xffffffffu, vv.x, 16);
                oy = __shfl_down_sync(0xffffffffu, vv.y, 16);
                oz = __shfl_down_sync(0xffffffffu, vv.z, 16);
                ow = __shfl_down_sync(0xffffffffu, vv.w, 16);
                if (eA4) { vv.x += ox; vv.y += oy; }
                if (eB4) { vv.z += oz; vv.w += ow; }
                if (headA) red_add_v2(g_msg + (size_t)dA * 128 + c, vv.x, vv.y);
                if (headB) red_add_v2(g_msg + (size_t)dB * 128 + c, vv.z, vv.w);
            }
        }

        if (hn) stage(cur ? sA0 : sA1, sAf + (cur ^ 1) * 1024, sDst + (cur ^ 1) * 128);
        __syncthreads();
        cur ^= 1;
    }
}

// ---------------- final: x += msg @ Wo; reset counters for next call ----------------
__global__ __launch_bounds__(512) void k_out(float* __restrict__ x,
                                             const float* __restrict__ Wo) {
    extern __shared__ float sm[];
    float* sA  = sm;
    float* sBt = sA + 16384;
    int tid = threadIdx.x, lane = tid & 31, w = tid >> 5;
    int wm = w & 3, wn = w >> 2;
    int g = lane >> 2, t4 = lane & 3;
    int n0 = blockIdx.x * 128;

    int gidx = blockIdx.x * 512 + tid;
    if (gidx < NA) { g_cnt_all[gidx] = 0; g_cnt_live[gidx] = 0; }

    for (int i = tid; i < 128 * 128; i += 512) {
        int r = i >> 7, c = i & 127;
        int n = n0 + r;
        sA[fragA_idx<16>(r, c)] = (n < NA) ? f2tff(g_msg[(size_t)n * 128 + c]) : 0.f;
    }
    for (int i = tid; i < 128 * 128; i += 512) {
        int k = i >> 7, n = i & 127;
        sBt[fragB_idx<16>(k, n)] = f2tff(Wo[i]);
    }
    __syncthreads();

    float4 acc[2][4];
    zacc4(acc);
    mma_tile_frag<16>(sA, sBt, wm, wn, lane, acc);
#pragma unroll
    for (int mi = 0; mi < 2; mi++) {
        int r = 32 * wm + 16 * mi + g;
#pragma unroll
        for (int jl = 0; jl < 4; jl++) {
            int c = 32 * wn + 8 * jl + 2 * t4;
            float4 d = acc[mi][jl];
            int n1 = n0 + r, n2 = n1 + 8;
            if (n1 < NA) {
                float2 o = *(float2*)(x + (size_t)n1 * 128 + c);
                o.x += d.x; o.y += d.y;
                *(float2*)(x + (size_t)n1 * 128 + c) = o;
            }
            if (n2 < NA) {
                float2 o = *(float2*)(x + (size_t)n2 * 128 + c);
                o.x += d.z; o.y += d.w;
                *(float2*)(x + (size_t)n2 * 128 + c) = o;
            }
        }
    }
}

// ---------------- launch ----------------
extern "C" void kernel_launch(void* const* d_in, const int* in_sizes, int n_in,
                              void* d_out, int out_size) {
    const float* xyz = (const float*)d_in[0];
    const float* emb = (const float*)d_in[1];
    const float* te  = (const float*)d_in[2];
    const float* Wl  = (const float*)d_in[3];
    const float* bl  = (const float*)d_in[4];
    const float* W1f = (const float*)d_in[5];
    const float* b1f = (const float*)d_in[6];
    const float* W2f = (const float*)d_in[7];
    const float* b2f = (const float*)d_in[8];
    const float* Wq  = (const float*)d_in[9];
    const float* Wk  = (const float*)d_in[10];
    const float* Wv  = (const float*)d_in[11];
    const float* Wo  = (const float*)d_in[12];
    const int*   z   = (const int*)d_in[13];
    const int*   src = (const int*)d_in[14];
    const int*   dst = (const int*)d_in[15];
    float* x = (float*)d_out;

    const int SM_FILTER = (4096 + 16384 + 4096 + 4096 + 16384 + 4 * 128) * 4;
    const int SM_OQK    = (2 * 16384) * 4;
    const int SM_MSGV   = (3 * 16384 + 2 * 1024) * 4 + 2 * 128 * 4;   // 205824
    const int SM_OUT    = (2 * 16384) * 4;

    cudaFuncSetAttribute(k_filter, cudaFuncAttributeMaxDynamicSharedMemorySize, SM_FILTER);
    cudaFuncSetAttribute(k_oqk,    cudaFuncAttributeMaxDynamicSharedMemorySize, SM_OQK);
    cudaFuncSetAttribute(k_msgv,   cudaFuncAttributeMaxDynamicSharedMemorySize, SM_MSGV);
    cudaFuncSetAttribute(k_out,    cudaFuncAttributeMaxDynamicSharedMemorySize, SM_OUT);

    k_hist<<<NE / 256, 256>>>(xyz, src, dst);
    k_scan<<<1, 512>>>();
    k_scatter<<<NE / 256, 256>>>(xyz, src, dst);
    k_filter<<<NSM, 512, SM_FILTER>>>(xyz, Wl, bl, W1f, b1f, W2f, b2f);
    k_embed<<<(NA * DD + 255) / 256, 256>>>(emb, z, x);

    const int NBLK = (NA + 127) / 128;   // 157
    for (int it = 0; it < NIT; it++) {
        k_oqk<<<NBLK, 512, SM_OQK>>>(x, te, Wo, Wq, Wk, it);
        k_soft<<<(NA * 32 + 255) / 256, 256>>>();
        k_msgv<<<NSM, 512, SM_MSGV>>>(Wv);
    }
    k_out<<<NBLK, 512, SM_OUT>>>(x, Wo);
}

// round 9
// speedup vs baseline: 1.1598x; 1.1598x over previous
#include <cuda_runtime.h>
#include <math.h>
#include <stdint.h>

#define NA 20000
#define NE 640000
#define DD 128
#define GG 32
#define HH 8
#define NIT 4
#define NSM 148

// ---------------- device scratch ----------------
__device__ float    g_Wfil[(size_t)NE * DD];
__device__ int      g_ssrc[NE];     // src, sorted by dst
__device__ int      g_sdst[NE];
__device__ int      g_lsrc[NE];     // live subset, sorted by dst
__device__ int      g_lpos[NE];
__device__ int      g_ldst[NE];
__device__ int      g_cnt_all[NA];  // statically zero; re-zeroed by final k_out
__device__ int      g_cnt_live[NA];
__device__ int      g_off_all[NA];
__device__ int      g_off_live[NA];
__device__ int      g_nlive;
__device__ float    g_h[NA * DD];
__device__ float    g_Q[NA * DD];
__device__ float    g_K[NA * DD];
__device__ float    g_s[NE * HH];
__device__ float    g_msg[NA * DD];

__device__ __forceinline__ void red_add_v2(float* p, float x, float y) {
    asm volatile("red.global.add.v2.f32 [%0], {%1,%2};"
                 :: "l"(p), "f"(x), "f"(y) : "memory");
}
__device__ __forceinline__ float edge_r(const float* xyz, int s, int d) {
    float dx = xyz[3 * s]     - xyz[3 * d];
    float dy = xyz[3 * s + 1] - xyz[3 * d + 1];
    float dz = xyz[3 * s + 2] - xyz[3 * d + 2];
    return sqrtf(dx * dx + dy * dy + dz * dz + 1e-12f);
}

// ---------------- tf32 MMA core with fragment-major smem ----------------
__device__ __forceinline__ uint32_t f2tf(float f) {
    uint32_t u;
    asm("cvt.rna.tf32.f32 %0, %1;" : "=r"(u) : "f"(f));
    return u;
}
__device__ __forceinline__ float f2tff(float f) { return __uint_as_float(f2tf(f)); }

__device__ __forceinline__ void mma8(float4& d,
                                     uint32_t a0, uint32_t a1, uint32_t a2, uint32_t a3,
                                     uint32_t b0, uint32_t b1) {
    asm volatile(
        "mma.sync.aligned.m16n8k8.row.col.f32.tf32.tf32.f32 "
        "{%0,%1,%2,%3},{%4,%5,%6,%7},{%8,%9},{%0,%1,%2,%3};"
        : "+f"(d.x), "+f"(d.y), "+f"(d.z), "+f"(d.w)
        : "r"(a0), "r"(a1), "r"(a2), "r"(a3), "r"(b0), "r"(b1));
}
template <int KB>
__device__ __forceinline__ int fragA_idx(int r, int k) {
    return (((r >> 4) * KB + (k >> 3)) << 7) + (((r & 7) * 4 + (k & 3)) << 2)
         + ((r >> 3) & 1) + (((k >> 2) & 1) << 1);
}
template <int KB>
__device__ __forceinline__ int fragB_idx(int k, int n) {
    return (((n >> 4) * KB + (k >> 3)) << 7) + (((n & 7) * 4 + (k & 3)) << 2)
         + (((n >> 3) & 1) << 1) + ((k >> 2) & 1);
}
#define FAU(x) __float_as_uint(x)
template <int KB>
__device__ __forceinline__ void mma_tile_frag(const float* __restrict__ sA,
                                              const float* __restrict__ sB,
                                              int wm, int wn, int lane,
                                              float4 acc[2][4]) {
    const float4* A = (const float4*)sA;
    const float4* B = (const float4*)sB;
#pragma unroll
    for (int kk = 0; kk < KB; kk++) {
        float4 a0 = A[((2 * wm)     * KB + kk) * 32 + lane];
        float4 a1 = A[((2 * wm + 1) * KB + kk) * 32 + lane];
        float4 b0 = B[((2 * wn)     * KB + kk) * 32 + lane];
        float4 b1 = B[((2 * wn + 1) * KB + kk) * 32 + lane];
        mma8(acc[0][0], FAU(a0.x), FAU(a0.y), FAU(a0.z), FAU(a0.w), FAU(b0.x), FAU(b0.y));
        mma8(acc[1][0], FAU(a1.x), FAU(a1.y), FAU(a1.z), FAU(a1.w), FAU(b0.x), FAU(b0.y));
        mma8(acc[0][1], FAU(a0.x), FAU(a0.y), FAU(a0.z), FAU(a0.w), FAU(b0.z), FAU(b0.w));
        mma8(acc[1][1], FAU(a1.x), FAU(a1.y), FAU(a1.z), FAU(a1.w), FAU(b0.z), FAU(b0.w));
        mma8(acc[0][2], FAU(a0.x), FAU(a0.y), FAU(a0.z), FAU(a0.w), FAU(b1.x), FAU(b1.y));
        mma8(acc[1][2], FAU(a1.x), FAU(a1.y), FAU(a1.z), FAU(a1.w), FAU(b1.x), FAU(b1.y));
        mma8(acc[0][3], FAU(a0.x), FAU(a0.y), FAU(a0.z), FAU(a0.w), FAU(b1.z), FAU(b1.w));
        mma8(acc[1][3], FAU(a1.x), FAU(a1.y), FAU(a1.z), FAU(a1.w), FAU(b1.z), FAU(b1.w));
    }
}
__device__ __forceinline__ void zacc4(float4 acc[2][4]) {
#pragma unroll
    for (int i = 0; i < 2; i++)
#pragma unroll
        for (int j = 0; j < 4; j++) acc[i][j] = make_float4(0.f, 0.f, 0.f, 0.f);
}

// ---------------- setup ----------------
__global__ void k_hist(const float* __restrict__ xyz, const int* __restrict__ src,
                       const int* __restrict__ dst) {
    int e = blockIdx.x * blockDim.x + threadIdx.x;
    if (e >= NE) return;
    int s = src[e], d = dst[e];
    atomicAdd(&g_cnt_all[d], 1);
    if (edge_r(xyz, s, d) < 8.f) atomicAdd(&g_cnt_live[d], 1);
}

__global__ __launch_bounds__(512) void k_scan() {
    __shared__ int part[512];
    __shared__ int total;
    int t = threadIdx.x;
    const int CH = (NA + 511) / 512;
#pragma unroll 1
    for (int pass = 0; pass < 2; pass++) {
        int* cnt = pass ? g_cnt_live : g_cnt_all;
        int* off = pass ? g_off_live : g_off_all;
        int lo = t * CH, hi = min(lo + CH, NA);
        int s = 0;
        for (int i = lo; i < hi; i++) s += cnt[i];
        part[t] = s;
        __syncthreads();
        if (t == 0) {
            int run = 0;
            for (int i = 0; i < 512; i++) { int v = part[i]; part[i] = run; run += v; }
            total = run;
        }
        __syncthreads();
        int run = part[t];
        for (int i = lo; i < hi; i++) { int v = cnt[i]; off[i] = run; run += v; cnt[i] = 0; }
        if (pass == 1 && t == 0) g_nlive = total;
        __syncthreads();
    }
}

__global__ void k_scatter(const float* __restrict__ xyz, const int* __restrict__ src,
                          const int* __restrict__ dst) {
    int e = blockIdx.x * blockDim.x + threadIdx.x;
    if (e >= NE) return;
    int s = src[e], d = dst[e];
    int pos = g_off_all[d] + atomicAdd(&g_cnt_all[d], 1);
    g_ssrc[pos] = s;
    g_sdst[pos] = d;
    if (edge_r(xyz, s, d) < 8.f) {
        int lp = g_off_live[d] + atomicAdd(&g_cnt_live[d], 1);
        g_lsrc[lp] = s; g_ldst[lp] = d; g_lpos[lp] = pos;
    }
}

__global__ void k_embed(const float* __restrict__ emb, const int* __restrict__ z,
                        float* __restrict__ x) {
    int i = blockIdx.x * blockDim.x + threadIdx.x;
    if (i < NA * DD) {
        int n = i >> 7, d = i & 127;
        x[i] = emb[z[n] * DD + d];
    }
}

// ---------------- filter (persistent, tf32, fragment smem) ----------------
__global__ __launch_bounds__(512) void k_filter(
    const float* __restrict__ xyz,
    const float* __restrict__ Wl, const float* __restrict__ bl,
    const float* __restrict__ W1f, const float* __restrict__ b1f,
    const float* __restrict__ W2f, const float* __restrict__ b2f) {
    extern __shared__ float sm[];
    float* sf   = sm;
    float* sg   = sf + 4096;
    float* sW1t = sg + 16384;
    float* sWlt = sW1t + 4096;
    float* sW2t = sWlt + 4096;
    float* sr   = sW2t + 16384;
    float* sC   = sr + 128;
    float* sb1  = sC + 128;
    float* sb   = sb1 + 128;

    int tid = threadIdx.x, lane = tid & 31, w = tid >> 5;
    int wm = w & 3, wn = w >> 2;
    int g = lane >> 2, t4 = lane & 3;

    for (int i = tid; i < 32 * 128; i += 512) {
        int k = i >> 7, n = i & 127;
        sW1t[fragB_idx<4>(k, n)] = f2tff(W1f[i]);
        sWlt[fragB_idx<4>(k, n)] = f2tff(Wl[i]);
    }
    for (int i = tid; i < 128 * 128; i += 512) {
        int k = i >> 7, n = i & 127;
        sW2t[fragB_idx<16>(k, n)] = f2tff(W2f[i]);
    }
    if (tid < 128) { sb1[tid] = b1f[tid]; sb[tid] = bl[tid] + b2f[tid]; }

    int nlive = g_nlive;
    for (int tt = blockIdx.x; tt * 128 < nlive; tt += gridDim.x) {
        if (tid < 128) {
            int li = tt * 128 + tid;
            float r = 100.f, C = 0.f;
            if (li < nlive) {
                r = edge_r(xyz, g_lsrc[li], g_ldst[li]);
                C = (r < 8.f) ? (0.5f * (cospif(r * 0.125f) + 1.f)) : 0.f;
            }
            sr[tid] = r; sC[tid] = C;
        }
        __syncthreads();
        {
            int el = tid >> 2, kb = (tid & 3) * 8;
            float r = sr[el];
#pragma unroll
            for (int q = 0; q < 8; q++) {
                int k = kb + q;
                float off = (float)k * (8.f / 31.f);
                float u = (r - off) * (31.f / 8.f);
                sf[fragA_idx<4>(el, k)] = f2tff(__expf(-0.5f * u * u));
            }
        }
        __syncthreads();

        float4 acc[2][4];
        zacc4(acc);
        mma_tile_frag<4>(sf, sW1t, wm, wn, lane, acc);
        __syncthreads();
#pragma unroll
        for (int mi = 0; mi < 2; mi++) {
            int r = 32 * wm + 16 * mi + g;
#pragma unroll
            for (int jl = 0; jl < 4; jl++) {
                int c = 32 * wn + 8 * jl + 2 * t4;
                float4 d = acc[mi][jl];
                float v0 = d.x + sb1[c], v1 = d.y + sb1[c + 1];
                float v2 = d.z + sb1[c], v3 = d.w + sb1[c + 1];
                sg[fragA_idx<16>(r, c)]         = f2tff(v0 / (1.f + __expf(-v0)));
                sg[fragA_idx<16>(r, c + 1)]     = f2tff(v1 / (1.f + __expf(-v1)));
                sg[fragA_idx<16>(r + 8, c)]     = f2tff(v2 / (1.f + __expf(-v2)));
                sg[fragA_idx<16>(r + 8, c + 1)] = f2tff(v3 / (1.f + __expf(-v3)));
            }
        }
        __syncthreads();

        zacc4(acc);
        mma_tile_frag<4>(sf, sWlt, wm, wn, lane, acc);
        mma_tile_frag<16>(sg, sW2t, wm, wn, lane, acc);

#pragma unroll
        for (int mi = 0; mi < 2; mi++) {
            int r = 32 * wm + 16 * mi + g;
#pragma unroll
            for (int jl = 0; jl < 4; jl++) {
                int c = 32 * wn + 8 * jl + 2 * t4;
                float4 d = acc[mi][jl];
                int li0 = tt * 128 + r, li1 = li0 + 8;
                if (li0 < nlive) {
                    float Cv = sC[r];
                    *(float2*)(g_Wfil + (size_t)li0 * 128 + c) =
                        make_float2((d.x + sb[c]) * Cv, (d.y + sb[c + 1]) * Cv);
                }
                if (li1 < nlive) {
                    float Cv = sC[r + 8];
                    *(float2*)(g_Wfil + (size_t)li1 * 128 + c) =
                        make_float2((d.z + sb[c]) * Cv, (d.w + sb[c + 1]) * Cv);
                }
            }
        }
        __syncthreads();
    }
}

// ---------------- fused out+hqk: x += msg@Wo; h = x+te; Q = h@Wq; K = h@Wk ----------------
__global__ __launch_bounds__(512) void k_oqk(float* __restrict__ x,
                                             const float* __restrict__ te,
                                             const float* __restrict__ Wo,
                                             const float* __restrict__ Wq,
                                             const float* __restrict__ Wk, int it) {
    extern __shared__ float sm[];
    float* sA = sm;
    float* sB = sm + 16384;
    int tid = threadIdx.x, lane = tid & 31, w = tid >> 5;
    int wm = w & 3, wn = w >> 2;
    int g = lane >> 2, t4 = lane & 3;
    int n0 = blockIdx.x * 128;

    float4 acc[2][4];
    zacc4(acc);
    if (it > 0) {
        for (int i = tid; i < 128 * 128; i += 512) {
            int r = i >> 7, c = i & 127, n = n0 + r;
            sA[fragA_idx<16>(r, c)] = (n < NA) ? f2tff(g_msg[(size_t)n * 128 + c]) : 0.f;
        }
        for (int i = tid; i < 128 * 128; i += 512) {
            int k = i >> 7, n = i & 127;
            sB[fragB_idx<16>(k, n)] = f2tff(Wo[i]);
        }
        __syncthreads();
        mma_tile_frag<16>(sA, sB, wm, wn, lane, acc);
        __syncthreads();
    }
#pragma unroll
    for (int mi = 0; mi < 2; mi++) {
        int r = 32 * wm + 16 * mi + g;
#pragma unroll
        for (int jl = 0; jl < 4; jl++) {
            int c = 32 * wn + 8 * jl + 2 * t4;
            float4 d = acc[mi][jl];
            float te0 = te[it * 128 + c], te1 = te[it * 128 + c + 1];
            int n1 = n0 + r, n2 = n1 + 8;
            float h00 = 0.f, h01 = 0.f, h10 = 0.f, h11 = 0.f;
            if (n1 < NA) {
                float2 xv = *(float2*)(x + (size_t)n1 * 128 + c);
                xv.x += d.x; xv.y += d.y;
                *(float2*)(x + (size_t)n1 * 128 + c) = xv;
                h00 = xv.x + te0; h01 = xv.y + te1;
                *(float2*)(g_h + (size_t)n1 * 128 + c) = make_float2(h00, h01);
            }
            if (n2 < NA) {
                float2 xv = *(float2*)(x + (size_t)n2 * 128 + c);
                xv.x += d.z; xv.y += d.w;
                *(float2*)(x + (size_t)n2 * 128 + c) = xv;
                h10 = xv.x + te0; h11 = xv.y + te1;
                *(float2*)(g_h + (size_t)n2 * 128 + c) = make_float2(h10, h11);
            }
            sA[fragA_idx<16>(r, c)]         = f2tff(h00);
            sA[fragA_idx<16>(r, c + 1)]     = f2tff(h01);
            sA[fragA_idx<16>(r + 8, c)]     = f2tff(h10);
            sA[fragA_idx<16>(r + 8, c + 1)] = f2tff(h11);
        }
    }
    for (int i = tid; i < 128 * 128; i += 512) {
        int k = i >> 7, n = i & 127;
        sB[fragB_idx<16>(k, n)] = f2tff(Wq[i]);
    }
    __syncthreads();
    zacc4(acc);
    mma_tile_frag<16>(sA, sB, wm, wn, lane, acc);
#pragma unroll
    for (int mi = 0; mi < 2; mi++) {
        int r = 32 * wm + 16 * mi + g;
#pragma unroll
        for (int jl = 0; jl < 4; jl++) {
            int c = 32 * wn + 8 * jl + 2 * t4;
            float4 d = acc[mi][jl];
            int n1 = n0 + r, n2 = n1 + 8;
            if (n1 < NA) *(float2*)(g_Q + (size_t)n1 * 128 + c) = make_float2(d.x, d.y);
            if (n2 < NA) *(float2*)(g_Q + (size_t)n2 * 128 + c) = make_float2(d.z, d.w);
        }
    }
    __syncthreads();
    for (int i = tid; i < 128 * 128; i += 512) {
        int k = i >> 7, n = i & 127;
        sB[fragB_idx<16>(k, n)] = f2tff(Wk[i]);
    }
    __syncthreads();
    zacc4(acc);
    mma_tile_frag<16>(sA, sB, wm, wn, lane, acc);
#pragma unroll
    for (int mi = 0; mi < 2; mi++) {
        int r = 32 * wm + 16 * mi + g;
#pragma unroll
        for (int jl = 0; jl < 4; jl++) {
            int c = 32 * wn + 8 * jl + 2 * t4;
            float4 d = acc[mi][jl];
            int n1 = n0 + r, n2 = n1 + 8;
            if (n1 < NA) *(float2*)(g_K + (size_t)n1 * 128 + c) = make_float2(d.x, d.y);
            if (n2 < NA) *(float2*)(g_K + (size_t)n2 * 128 + c) = make_float2(d.z, d.w);
        }
    }
}

// ---------------- fused per-atom softmax (online max/denominator) ----------------
__global__ __launch_bounds__(256) void k_soft() {
    int warp = (blockIdx.x * blockDim.x + threadIdx.x) >> 5;
    int lane = threadIdx.x & 31;
    if (warp >= NA) return;
    int d = warp;
    *(float4*)(g_msg + (size_t)d * 128 + lane * 4) = make_float4(0.f, 0.f, 0.f, 0.f);
    int beg = g_off_all[d], cnt = g_cnt_all[d];
    if (cnt == 0) return;

    float4 q = *(const float4*)(g_Q + (size_t)d * 128 + lane * 4);
    float m = -1e30f, den = 0.f;     // online, per 4-lane group (head = lane>>2)
    for (int i = 0; i < cnt; i++) {
        int e = beg + i;
        int s = g_ssrc[e];
        float4 kv = *(const float4*)(g_K + (size_t)s * 128 + lane * 4);
        float p = q.x * kv.x + q.y * kv.y + q.z * kv.z + q.w * kv.w;
        p += __shfl_xor_sync(0xffffffffu, p, 1);
        p += __shfl_xor_sync(0xffffffffu, p, 2);
        p *= 0.25f;
        float mn = fmaxf(m, p);
        den = den * __expf(m - mn) + __expf(p - mn);
        m = mn;
        float t = __shfl_sync(0xffffffffu, p, (lane & 7) * 4);
        if (lane < 8) g_s[(size_t)e * 8 + lane] = t;
    }
    // lane now handles head (lane&7); fetch that head's m, den
    float mh  = __shfl_sync(0xffffffffu, m,   (lane & 7) * 4);
    float dh  = __shfl_sync(0xffffffffu, den, (lane & 7) * 4);
    float inv = 1.f / (dh + 1e-12f);
    int h = lane & 7, eo = lane >> 3;
    for (int base = 0; base < cnt; base += 4) {
        int i = base + eo;
        if (i < cnt) {
            size_t o = (size_t)(beg + i) * 8 + h;
            g_s[o] = __expf(g_s[o] - mh) * inv;
        }
    }
}

// ---------------- msgv: tf32 MMA + in-register segmented reduce (R6 version) ----------------
__global__ __launch_bounds__(512) void k_msgv(const float* __restrict__ Wv) {
    extern __shared__ float sm[];
    float* sA   = sm;                  // frag A 16384
    float* sBt  = sA + 16384;          // frag B 16384
    float* sAf  = sBt + 16384;         // 128*8 attention weights
    int*   sDst = (int*)(sAf + 128 * 8);
    int tid = threadIdx.x, lane = tid & 31, w = tid >> 5;
    int wm = w & 3, wn = w >> 2;
    int g = lane >> 2, t4 = lane & 3;

    for (int i = tid; i < 128 * 128; i += 512) {
        int k = i >> 7, n = i & 127;
        sBt[fragB_idx<16>(k, n)] = f2tff(Wv[i]);
    }
    int nlive = g_nlive;

    for (int tt = blockIdx.x; tt * 128 < nlive; tt += gridDim.x) {
        if (tid < 128) {
            int li = tt * 128 + tid;
            if (li < nlive) {
                int d = g_ldst[li];
                int pos = g_lpos[li];
                sDst[tid] = d;
                *(float4*)(sAf + tid * 8)     = *(const float4*)(g_s + (size_t)pos * 8);
                *(float4*)(sAf + tid * 8 + 4) = *(const float4*)(g_s + (size_t)pos * 8 + 4);
            } else {
                sDst[tid] = -1;
                *(float4*)(sAf + tid * 8)     = make_float4(0.f, 0.f, 0.f, 0.f);
                *(float4*)(sAf + tid * 8 + 4) = make_float4(0.f, 0.f, 0.f, 0.f);
            }
        }
        {   // A = h[src] * Wfil -> frag layout. 4 threads/row, 32 k each
            int r = tid >> 2, cb = (tid & 3) * 32;
            int li = tt * 128 + r;
            if (li < nlive) {
                int s = g_lsrc[li];
                const float4* wf = (const float4*)(g_Wfil + (size_t)li * 128 + cb);
                const float4* hp = (const float4*)(g_h + (size_t)s * 128 + cb);
#pragma unroll
                for (int q = 0; q < 8; q++) {
                    float4 ww = wf[q], hh = hp[q];
                    int i0 = fragA_idx<16>(r, cb + q * 4);
                    sA[i0]      = f2tff(ww.x * hh.x);
                    sA[i0 + 4]  = f2tff(ww.y * hh.y);
                    sA[i0 + 8]  = f2tff(ww.z * hh.z);
                    sA[i0 + 12] = f2tff(ww.w * hh.w);
                }
            } else {
#pragma unroll
                for (int q = 0; q < 8; q++) {
                    int i0 = fragA_idx<16>(r, cb + q * 4);
                    sA[i0] = 0.f; sA[i0 + 4] = 0.f; sA[i0 + 8] = 0.f; sA[i0 + 12] = 0.f;
                }
            }
        }
        __syncthreads();

        float4 acc[2][4];
        zacc4(acc);
        mma_tile_frag<16>(sA, sBt, wm, wn, lane, acc);

        // in-register epilogue: a ⊙ v, then dst-segmented reduce over the 8 g-rows
#pragma unroll
        for (int mi = 0; mi < 2; mi++) {
            int r = 32 * wm + 16 * mi + g;
            int dA = sDst[r], dB = sDst[r + 8];
            int odA1 = __shfl_down_sync(0xffffffffu, dA, 4);
            int odB1 = __shfl_down_sync(0xffffffffu, dB, 4);
            int odA2 = __shfl_down_sync(0xffffffffu, dA, 8);
            int odB2 = __shfl_down_sync(0xffffffffu, dB, 8);
            int odA4 = __shfl_down_sync(0xffffffffu, dA, 16);
            int odB4 = __shfl_down_sync(0xffffffffu, dB, 16);
            bool eA1 = (g + 1 < 8) && (odA1 == dA);
            bool eB1 = (g + 1 < 8) && (odB1 == dB);
            bool eA2 = (g + 2 < 8) && (odA2 == dA);
            bool eB2 = (g + 2 < 8) && (odB2 == dB);
            bool eA4 = (g + 4 < 8) && (odA4 == dA);
            bool eB4 = (g + 4 < 8) && (odB4 == dB);
            int pdA = __shfl_up_sync(0xffffffffu, dA, 4);
            int pdB = __shfl_up_sync(0xffffffffu, dB, 4);
            bool headA = (dA >= 0) && (g == 0 || pdA != dA);
            bool headB = (dB >= 0) && (g == 0 || pdB != dB);
#pragma unroll
            for (int jl = 0; jl < 4; jl++) {
                int c = 32 * wn + 8 * jl + 2 * t4;
                int head = c >> 4;
                float aA = sAf[r * 8 + head];
                float aB = sAf[(r + 8) * 8 + head];
                float4 v = acc[mi][jl];
                v.x *= aA; v.y *= aA; v.z *= aB; v.w *= aB;
                float ox, oy, oz, ow;
                ox = __shfl_down_sync(0xffffffffu, v.x, 4);
                oy = __shfl_down_sync(0xffffffffu, v.y, 4);
                oz = __shfl_down_sync(0xffffffffu, v.z, 4);
                ow = __shfl_down_sync(0xffffffffu, v.w, 4);
                if (eA1) { v.x += ox; v.y += oy; }
                if (eB1) { v.z += oz; v.w += ow; }
                ox = __shfl_down_sync(0xffffffffu, v.x, 8);
                oy = __shfl_down_sync(0xffffffffu, v.y, 8);
                oz = __shfl_down_sync(0xffffffffu, v.z, 8);
                ow = __shfl_down_sync(0xffffffffu, v.w, 8);
                if (eA2) { v.x += ox; v.y += oy; }
                if (eB2) { v.z += oz; v.w += ow; }
                ox = __shfl_down_sync(0xffffffffu, v.x, 16);
                oy = __shfl_down_sync(0xffffffffu, v.y, 16);
                oz = __shfl_down_sync(0xffffffffu, v.z, 16);
                ow = __shfl_down_sync(0xffffffffu, v.w, 16);
                if (eA4) { v.x += ox; v.y += oy; }
                if (eB4) { v.z += oz; v.w += ow; }
                if (headA) red_add_v2(g_msg + (size_t)dA * 128 + c, v.x, v.y);
                if (headB) red_add_v2(g_msg + (size_t)dB * 128 + c, v.z, v.w);
            }
        }
        __syncthreads();
    }
}

// ---------------- final: x += msg @ Wo; reset counters for next call ----------------
__global__ __launch_bounds__(512) void k_out(float* __restrict__ x,
                                             const float* __restrict__ Wo) {
    extern __shared__ float sm[];
    float* sA  = sm;
    float* sBt = sA + 16384;
    int tid = threadIdx.x, lane = tid & 31, w = tid >> 5;
    int wm = w & 3, wn = w >> 2;
    int g = lane >> 2, t4 = lane & 3;
    int n0 = blockIdx.x * 128;

    int gidx = blockIdx.x * 512 + tid;
    if (gidx < NA) { g_cnt_all[gidx] = 0; g_cnt_live[gidx] = 0; }

    for (int i = tid; i < 128 * 128; i += 512) {
        int r = i >> 7, c = i & 127;
        int n = n0 + r;
        sA[fragA_idx<16>(r, c)] = (n < NA) ? f2tff(g_msg[(size_t)n * 128 + c]) : 0.f;
    }
    for (int i = tid; i < 128 * 128; i += 512) {
        int k = i >> 7, n = i & 127;
        sBt[fragB_idx<16>(k, n)] = f2tff(Wo[i]);
    }
    __syncthreads();

    float4 acc[2][4];
    zacc4(acc);
    mma_tile_frag<16>(sA, sBt, wm, wn, lane, acc);
#pragma unroll
    for (int mi = 0; mi < 2; mi++) {
        int r = 32 * wm + 16 * mi + g;
#pragma unroll
        for (int jl = 0; jl < 4; jl++) {
            int c = 32 * wn + 8 * jl + 2 * t4;
            float4 d = acc[mi][jl];
            int n1 = n0 + r, n2 = n1 + 8;
            if (n1 < NA) {
                float2 o = *(float2*)(x + (size_t)n1 * 128 + c);
                o.x += d.x; o.y += d.y;
                *(float2*)(x + (size_t)n1 * 128 + c) = o;
            }
            if (n2 < NA) {
                float2 o = *(float2*)(x + (size_t)n2 * 128 + c);
                o.x += d.z; o.y += d.w;
                *(float2*)(x + (size_t)n2 * 128 + c) = o;
            }
        }
    }
}

// ---------------- launch ----------------
extern "C" void kernel_launch(void* const* d_in, const int* in_sizes, int n_in,
                              void* d_out, int out_size) {
    const float* xyz = (const float*)d_in[0];
    const float* emb = (const float*)d_in[1];
    const float* te  = (const float*)d_in[2];
    const float* Wl  = (const float*)d_in[3];
    const float* bl  = (const float*)d_in[4];
    const float* W1f = (const float*)d_in[5];
    const float* b1f = (const float*)d_in[6];
    const float* W2f = (const float*)d_in[7];
    const float* b2f = (const float*)d_in[8];
    const float* Wq  = (const float*)d_in[9];
    const float* Wk  = (const float*)d_in[10];
    const float* Wv  = (const float*)d_in[11];
    const float* Wo  = (const float*)d_in[12];
    const int*   z   = (const int*)d_in[13];
    const int*   src = (const int*)d_in[14];
    const int*   dst = (const int*)d_in[15];
    float* x = (float*)d_out;

    const int SM_FILTER = (4096 + 16384 + 4096 + 4096 + 16384 + 4 * 128) * 4;
    const int SM_OQK    = (2 * 16384) * 4;
    const int SM_MSGV   = (2 * 16384 + 128 * 8 + 128) * 4;
    const int SM_OUT    = (2 * 16384) * 4;

    cudaFuncSetAttribute(k_filter, cudaFuncAttributeMaxDynamicSharedMemorySize, SM_FILTER);
    cudaFuncSetAttribute(k_oqk,    cudaFuncAttributeMaxDynamicSharedMemorySize, SM_OQK);
    cudaFuncSetAttribute(k_msgv,   cudaFuncAttributeMaxDynamicSharedMemorySize, SM_MSGV);
    cudaFuncSetAttribute(k_out,    cudaFuncAttributeMaxDynamicSharedMemorySize, SM_OUT);

    k_hist<<<NE / 256, 256>>>(xyz, src, dst);
    k_scan<<<1, 512>>>();
    k_scatter<<<NE / 256, 256>>>(xyz, src, dst);
    k_filter<<<NSM, 512, SM_FILTER>>>(xyz, Wl, bl, W1f, b1f, W2f, b2f);
    k_embed<<<(NA * DD + 255) / 256, 256>>>(emb, z, x);

    const int NBLK = (NA + 127) / 128;   // 157
    for (int it = 0; it < NIT; it++) {
        k_oqk<<<NBLK, 512, SM_OQK>>>(x, te, Wo, Wq, Wk, it);
        k_soft<<<(NA * 32 + 255) / 256, 256>>>();
        k_msgv<<<NSM, 512, SM_MSGV>>>(Wv);
    }
    k_out<<<NBLK, 512, SM_OUT>>>(x, Wo);
}

// round 10
// speedup vs baseline: 1.4255x; 1.2290x over previous
#include <cuda_runtime.h>
#include <math.h>
#include <stdint.h>

#define NA 20000
#define NE 640000
#define DD 128
#define GG 32
#define HH 8
#define NIT 4
#define NSM 148

// ---------------- device scratch ----------------
__device__ float    g_Wfil[(size_t)NE * DD];
__device__ int      g_ssrc[NE];     // src, sorted by dst
__device__ int      g_sdst[NE];
__device__ int      g_lsrc[NE];     // live subset, sorted by dst
__device__ int      g_lpos[NE];
__device__ int      g_ldst[NE];
__device__ int      g_cnt_all[NA];  // statically zero; re-zeroed by final k_out
__device__ int      g_cnt_live[NA];
__device__ int      g_off_all[NA];
__device__ int      g_off_live[NA];
__device__ int      g_nlive;
__device__ float    g_h[NA * DD];
__device__ float    g_Q[NA * DD];
__device__ float    g_K[NA * DD];
__device__ float    g_s[NE * HH];
__device__ float    g_U[(size_t)NA * 1024];   // per-atom [8 heads][128 dims] aggregate
__device__ float    g_msg[NA * DD];

__device__ __forceinline__ float edge_r(const float* xyz, int s, int d) {
    float dx = xyz[3 * s]     - xyz[3 * d];
    float dy = xyz[3 * s + 1] - xyz[3 * d + 1];
    float dz = xyz[3 * s + 2] - xyz[3 * d + 2];
    return sqrtf(dx * dx + dy * dy + dz * dz + 1e-12f);
}

// ---------------- tf32 MMA core with fragment-major smem ----------------
__device__ __forceinline__ uint32_t f2tf(float f) {
    uint32_t u;
    asm("cvt.rna.tf32.f32 %0, %1;" : "=r"(u) : "f"(f));
    return u;
}
__device__ __forceinline__ float f2tff(float f) { return __uint_as_float(f2tf(f)); }

__device__ __forceinline__ void mma8(float4& d,
                                     uint32_t a0, uint32_t a1, uint32_t a2, uint32_t a3,
                                     uint32_t b0, uint32_t b1) {
    asm volatile(
        "mma.sync.aligned.m16n8k8.row.col.f32.tf32.tf32.f32 "
        "{%0,%1,%2,%3},{%4,%5,%6,%7},{%8,%9},{%0,%1,%2,%3};"
        : "+f"(d.x), "+f"(d.y), "+f"(d.z), "+f"(d.w)
        : "r"(a0), "r"(a1), "r"(a2), "r"(a3), "r"(b0), "r"(b1));
}
template <int KB>
__device__ __forceinline__ int fragA_idx(int r, int k) {
    return (((r >> 4) * KB + (k >> 3)) << 7) + (((r & 7) * 4 + (k & 3)) << 2)
         + ((r >> 3) & 1) + (((k >> 2) & 1) << 1);
}
template <int KB>
__device__ __forceinline__ int fragB_idx(int k, int n) {
    return (((n >> 4) * KB + (k >> 3)) << 7) + (((n & 7) * 4 + (k & 3)) << 2)
         + (((n >> 3) & 1) << 1) + ((k >> 2) & 1);
}
#define FAU(x) __float_as_uint(x)
template <int KB>
__device__ __forceinline__ void mma_tile_frag(const float* __restrict__ sA,
                                              const float* __restrict__ sB,
                                              int wm, int wn, int lane,
                                              float4 acc[2][4]) {
    const float4* A = (const float4*)sA;
    const float4* B = (const float4*)sB;
#pragma unroll
    for (int kk = 0; kk < KB; kk++) {
        float4 a0 = A[((2 * wm)     * KB + kk) * 32 + lane];
        float4 a1 = A[((2 * wm + 1) * KB + kk) * 32 + lane];
        float4 b0 = B[((2 * wn)     * KB + kk) * 32 + lane];
        float4 b1 = B[((2 * wn + 1) * KB + kk) * 32 + lane];
        mma8(acc[0][0], FAU(a0.x), FAU(a0.y), FAU(a0.z), FAU(a0.w), FAU(b0.x), FAU(b0.y));
        mma8(acc[1][0], FAU(a1.x), FAU(a1.y), FAU(a1.z), FAU(a1.w), FAU(b0.x), FAU(b0.y));
        mma8(acc[0][1], FAU(a0.x), FAU(a0.y), FAU(a0.z), FAU(a0.w), FAU(b0.z), FAU(b0.w));
        mma8(acc[1][1], FAU(a1.x), FAU(a1.y), FAU(a1.z), FAU(a1.w), FAU(b0.z), FAU(b0.w));
        mma8(acc[0][2], FAU(a0.x), FAU(a0.y), FAU(a0.z), FAU(a0.w), FAU(b1.x), FAU(b1.y));
        mma8(acc[1][2], FAU(a1.x), FAU(a1.y), FAU(a1.z), FAU(a1.w), FAU(b1.x), FAU(b1.y));
        mma8(acc[0][3], FAU(a0.x), FAU(a0.y), FAU(a0.z), FAU(a0.w), FAU(b1.z), FAU(b1.w));
        mma8(acc[1][3], FAU(a1.x), FAU(a1.y), FAU(a1.z), FAU(a1.w), FAU(b1.z), FAU(b1.w));
    }
}
__device__ __forceinline__ void zacc4(float4 acc[2][4]) {
#pragma unroll
    for (int i = 0; i < 2; i++)
#pragma unroll
        for (int j = 0; j < 4; j++) acc[i][j] = make_float4(0.f, 0.f, 0.f, 0.f);
}

// ---------------- setup ----------------
__global__ void k_hist(const float* __restrict__ xyz, const int* __restrict__ src,
                       const int* __restrict__ dst) {
    int e = blockIdx.x * blockDim.x + threadIdx.x;
    if (e >= NE) return;
    int s = src[e], d = dst[e];
    atomicAdd(&g_cnt_all[d], 1);
    if (edge_r(xyz, s, d) < 8.f) atomicAdd(&g_cnt_live[d], 1);
}

__global__ __launch_bounds__(512) void k_scan() {
    __shared__ int part[512];
    __shared__ int total;
    int t = threadIdx.x;
    const int CH = (NA + 511) / 512;
#pragma unroll 1
    for (int pass = 0; pass < 2; pass++) {
        int* cnt = pass ? g_cnt_live : g_cnt_all;
        int* off = pass ? g_off_live : g_off_all;
        int lo = t * CH, hi = min(lo + CH, NA);
        int s = 0;
        for (int i = lo; i < hi; i++) s += cnt[i];
        part[t] = s;
        __syncthreads();
        if (t == 0) {
            int run = 0;
            for (int i = 0; i < 512; i++) { int v = part[i]; part[i] = run; run += v; }
            total = run;
        }
        __syncthreads();
        int run = part[t];
        for (int i = lo; i < hi; i++) { int v = cnt[i]; off[i] = run; run += v; cnt[i] = 0; }
        if (pass == 1 && t == 0) g_nlive = total;
        __syncthreads();
    }
}

__global__ void k_scatter(const float* __restrict__ xyz, const int* __restrict__ src,
                          const int* __restrict__ dst) {
    int e = blockIdx.x * blockDim.x + threadIdx.x;
    if (e >= NE) return;
    int s = src[e], d = dst[e];
    int pos = g_off_all[d] + atomicAdd(&g_cnt_all[d], 1);
    g_ssrc[pos] = s;
    g_sdst[pos] = d;
    if (edge_r(xyz, s, d) < 8.f) {
        int lp = g_off_live[d] + atomicAdd(&g_cnt_live[d], 1);
        g_lsrc[lp] = s; g_ldst[lp] = d; g_lpos[lp] = pos;
    }
}

__global__ void k_embed(const float* __restrict__ emb, const int* __restrict__ z,
                        float* __restrict__ x) {
    int i = blockIdx.x * blockDim.x + threadIdx.x;
    if (i < NA * DD) {
        int n = i >> 7, d = i & 127;
        x[i] = emb[z[n] * DD + d];
    }
}

// ---------------- filter (persistent, tf32, fragment smem) ----------------
__global__ __launch_bounds__(512) void k_filter(
    const float* __restrict__ xyz,
    const float* __restrict__ Wl, const float* __restrict__ bl,
    const float* __restrict__ W1f, const float* __restrict__ b1f,
    const float* __restrict__ W2f, const float* __restrict__ b2f) {
    extern __shared__ float sm[];
    float* sf   = sm;
    float* sg   = sf + 4096;
    float* sW1t = sg + 16384;
    float* sWlt = sW1t + 4096;
    float* sW2t = sWlt + 4096;
    float* sr   = sW2t + 16384;
    float* sC   = sr + 128;
    float* sb1  = sC + 128;
    float* sb   = sb1 + 128;

    int tid = threadIdx.x, lane = tid & 31, w = tid >> 5;
    int wm = w & 3, wn = w >> 2;
    int g = lane >> 2, t4 = lane & 3;

    for (int i = tid; i < 32 * 128; i += 512) {
        int k = i >> 7, n = i & 127;
        sW1t[fragB_idx<4>(k, n)] = f2tff(W1f[i]);
        sWlt[fragB_idx<4>(k, n)] = f2tff(Wl[i]);
    }
    for (int i = tid; i < 128 * 128; i += 512) {
        int k = i >> 7, n = i & 127;
        sW2t[fragB_idx<16>(k, n)] = f2tff(W2f[i]);
    }
    if (tid < 128) { sb1[tid] = b1f[tid]; sb[tid] = bl[tid] + b2f[tid]; }

    int nlive = g_nlive;
    for (int tt = blockIdx.x; tt * 128 < nlive; tt += gridDim.x) {
        if (tid < 128) {
            int li = tt * 128 + tid;
            float r = 100.f, C = 0.f;
            if (li < nlive) {
                r = edge_r(xyz, g_lsrc[li], g_ldst[li]);
                C = (r < 8.f) ? (0.5f * (cospif(r * 0.125f) + 1.f)) : 0.f;
            }
            sr[tid] = r; sC[tid] = C;
        }
        __syncthreads();
        {
            int el = tid >> 2, kb = (tid & 3) * 8;
            float r = sr[el];
#pragma unroll
            for (int q = 0; q < 8; q++) {
                int k = kb + q;
                float off = (float)k * (8.f / 31.f);
                float u = (r - off) * (31.f / 8.f);
                sf[fragA_idx<4>(el, k)] = f2tff(__expf(-0.5f * u * u));
            }
        }
        __syncthreads();

        float4 acc[2][4];
        zacc4(acc);
        mma_tile_frag<4>(sf, sW1t, wm, wn, lane, acc);
        __syncthreads();
#pragma unroll
        for (int mi = 0; mi < 2; mi++) {
            int r = 32 * wm + 16 * mi + g;
#pragma unroll
            for (int jl = 0; jl < 4; jl++) {
                int c = 32 * wn + 8 * jl + 2 * t4;
                float4 d = acc[mi][jl];
                float v0 = d.x + sb1[c], v1 = d.y + sb1[c + 1];
                float v2 = d.z + sb1[c], v3 = d.w + sb1[c + 1];
                sg[fragA_idx<16>(r, c)]         = f2tff(v0 / (1.f + __expf(-v0)));
                sg[fragA_idx<16>(r, c + 1)]     = f2tff(v1 / (1.f + __expf(-v1)));
                sg[fragA_idx<16>(r + 8, c)]     = f2tff(v2 / (1.f + __expf(-v2)));
                sg[fragA_idx<16>(r + 8, c + 1)] = f2tff(v3 / (1.f + __expf(-v3)));
            }
        }
        __syncthreads();

        zacc4(acc);
        mma_tile_frag<4>(sf, sWlt, wm, wn, lane, acc);
        mma_tile_frag<16>(sg, sW2t, wm, wn, lane, acc);

#pragma unroll
        for (int mi = 0; mi < 2; mi++) {
            int r = 32 * wm + 16 * mi + g;
#pragma unroll
            for (int jl = 0; jl < 4; jl++) {
                int c = 32 * wn + 8 * jl + 2 * t4;
                float4 d = acc[mi][jl];
                int li0 = tt * 128 + r, li1 = li0 + 8;
                if (li0 < nlive) {
                    float Cv = sC[r];
                    *(float2*)(g_Wfil + (size_t)li0 * 128 + c) =
                        make_float2((d.x + sb[c]) * Cv, (d.y + sb[c + 1]) * Cv);
                }
                if (li1 < nlive) {
                    float Cv = sC[r + 8];
                    *(float2*)(g_Wfil + (size_t)li1 * 128 + c) =
                        make_float2((d.z + sb[c]) * Cv, (d.w + sb[c + 1]) * Cv);
                }
            }
        }
        __syncthreads();
    }
}

// ---------------- fused out+hqk: x += msg@Wo; h = x+te; Q = h@Wq; K = h@Wk ----------------
__global__ __launch_bounds__(512) void k_oqk(float* __restrict__ x,
                                             const float* __restrict__ te,
                                             const float* __restrict__ Wo,
                                             const float* __restrict__ Wq,
                                             const float* __restrict__ Wk, int it) {
    extern __shared__ float sm[];
    float* sA = sm;
    float* sB = sm + 16384;
    int tid = threadIdx.x, lane = tid & 31, w = tid >> 5;
    int wm = w & 3, wn = w >> 2;
    int g = lane >> 2, t4 = lane & 3;
    int n0 = blockIdx.x * 128;

    float4 acc[2][4];
    zacc4(acc);
    if (it > 0) {
        for (int i = tid; i < 128 * 128; i += 512) {
            int r = i >> 7, c = i & 127, n = n0 + r;
            sA[fragA_idx<16>(r, c)] = (n < NA) ? f2tff(g_msg[(size_t)n * 128 + c]) : 0.f;
        }
        for (int i = tid; i < 128 * 128; i += 512) {
            int k = i >> 7, n = i & 127;
            sB[fragB_idx<16>(k, n)] = f2tff(Wo[i]);
        }
        __syncthreads();
        mma_tile_frag<16>(sA, sB, wm, wn, lane, acc);
        __syncthreads();
    }
#pragma unroll
    for (int mi = 0; mi < 2; mi++) {
        int r = 32 * wm + 16 * mi + g;
#pragma unroll
        for (int jl = 0; jl < 4; jl++) {
            int c = 32 * wn + 8 * jl + 2 * t4;
            float4 d = acc[mi][jl];
            float te0 = te[it * 128 + c], te1 = te[it * 128 + c + 1];
            int n1 = n0 + r, n2 = n1 + 8;
            float h00 = 0.f, h01 = 0.f, h10 = 0.f, h11 = 0.f;
            if (n1 < NA) {
                float2 xv = *(float2*)(x + (size_t)n1 * 128 + c);
                xv.x += d.x; xv.y += d.y;
                *(float2*)(x + (size_t)n1 * 128 + c) = xv;
                h00 = xv.x + te0; h01 = xv.y + te1;
                *(float2*)(g_h + (size_t)n1 * 128 + c) = make_float2(h00, h01);
            }
            if (n2 < NA) {
                float2 xv = *(float2*)(x + (size_t)n2 * 128 + c);
                xv.x += d.z; xv.y += d.w;
                *(float2*)(x + (size_t)n2 * 128 + c) = xv;
                h10 = xv.x + te0; h11 = xv.y + te1;
                *(float2*)(g_h + (size_t)n2 * 128 + c) = make_float2(h10, h11);
            }
            sA[fragA_idx<16>(r, c)]         = f2tff(h00);
            sA[fragA_idx<16>(r, c + 1)]     = f2tff(h01);
            sA[fragA_idx<16>(r + 8, c)]     = f2tff(h10);
            sA[fragA_idx<16>(r + 8, c + 1)] = f2tff(h11);
        }
    }
    for (int i = tid; i < 128 * 128; i += 512) {
        int k = i >> 7, n = i & 127;
        sB[fragB_idx<16>(k, n)] = f2tff(Wq[i]);
    }
    __syncthreads();
    zacc4(acc);
    mma_tile_frag<16>(sA, sB, wm, wn, lane, acc);
#pragma unroll
    for (int mi = 0; mi < 2; mi++) {
        int r = 32 * wm + 16 * mi + g;
#pragma unroll
        for (int jl = 0; jl < 4; jl++) {
            int c = 32 * wn + 8 * jl + 2 * t4;
            float4 d = acc[mi][jl];
            int n1 = n0 + r, n2 = n1 + 8;
            if (n1 < NA) *(float2*)(g_Q + (size_t)n1 * 128 + c) = make_float2(d.x, d.y);
            if (n2 < NA) *(float2*)(g_Q + (size_t)n2 * 128 + c) = make_float2(d.z, d.w);
        }
    }
    __syncthreads();
    for (int i = tid; i < 128 * 128; i += 512) {
        int k = i >> 7, n = i & 127;
        sB[fragB_idx<16>(k, n)] = f2tff(Wk[i]);
    }
    __syncthreads();
    zacc4(acc);
    mma_tile_frag<16>(sA, sB, wm, wn, lane, acc);
#pragma unroll
    for (int mi = 0; mi < 2; mi++) {
        int r = 32 * wm + 16 * mi + g;
#pragma unroll
        for (int jl = 0; jl < 4; jl++) {
            int c = 32 * wn + 8 * jl + 2 * t4;
            float4 d = acc[mi][jl];
            int n1 = n0 + r, n2 = n1 + 8;
            if (n1 < NA) *(float2*)(g_K + (size_t)n1 * 128 + c) = make_float2(d.x, d.y);
            if (n2 < NA) *(float2*)(g_K + (size_t)n2 * 128 + c) = make_float2(d.z, d.w);
        }
    }
}

// ---------------- fused attention: softmax + per-atom U aggregation ----------------
// one warp per dst atom; edges dst-sorted
__global__ __launch_bounds__(256) void k_attn() {
    int warp = (blockIdx.x * blockDim.x + threadIdx.x) >> 5;
    int lane = threadIdx.x & 31;
    if (warp >= NA) return;
    int d = warp;
    int beg = g_off_all[d], cnt = g_cnt_all[d];

    float acc[8][4];
#pragma unroll
    for (int b = 0; b < 8; b++)
#pragma unroll
        for (int j = 0; j < 4; j++) acc[b][j] = 0.f;

    if (cnt > 0) {
        // pass 1: scores + online per-head max/denominator
        float4 q = *(const float4*)(g_Q + (size_t)d * 128 + lane * 4);
        float m = -1e30f, den = 0.f;
        for (int i = 0; i < cnt; i++) {
            int e = beg + i;
            int s = g_ssrc[e];
            float4 kv = *(const float4*)(g_K + (size_t)s * 128 + lane * 4);
            float p = q.x * kv.x + q.y * kv.y + q.z * kv.z + q.w * kv.w;
            p += __shfl_xor_sync(0xffffffffu, p, 1);
            p += __shfl_xor_sync(0xffffffffu, p, 2);
            p *= 0.25f;
            float mn = fmaxf(m, p);
            den = den * __expf(m - mn) + __expf(p - mn);
            m = mn;
            float t = __shfl_sync(0xffffffffu, p, (lane & 7) * 4);
            if (lane < 8) g_s[(size_t)e * 8 + lane] = t;
        }
        __syncwarp();
        // pass 2: normalize a into g_s
        float mh  = __shfl_sync(0xffffffffu, m,   (lane & 7) * 4);
        float dh  = __shfl_sync(0xffffffffu, den, (lane & 7) * 4);
        float inv = 1.f / (dh + 1e-12f);
        int h = lane & 7, eo = lane >> 3;
        for (int base = 0; base < cnt; base += 4) {
            int i = base + eo;
            if (i < cnt) {
                size_t o = (size_t)(beg + i) * 8 + h;
                g_s[o] = __expf(g_s[o] - mh) * inv;
            }
        }
        __syncwarp();
        // pass 3: U[d][b][dim] = sum over live edges of a_b * (h[src] * Wfil)
        int lbeg = g_off_live[d], lcnt = g_cnt_live[d];
        for (int i = 0; i < lcnt; i++) {
            int lp = lbeg + i;
            int e = g_lpos[lp];
            int s = g_lsrc[lp];
            float4 a0 = *(const float4*)(g_s + (size_t)e * 8);
            float4 a1 = *(const float4*)(g_s + (size_t)e * 8 + 4);
            float4 hv = *(const float4*)(g_h + (size_t)s * 128 + lane * 4);
            float4 wv = *(const float4*)(g_Wfil + (size_t)lp * 128 + lane * 4);
            float u0 = hv.x * wv.x, u1 = hv.y * wv.y;
            float u2 = hv.z * wv.z, u3 = hv.w * wv.w;
            float ab[8] = {a0.x, a0.y, a0.z, a0.w, a1.x, a1.y, a1.z, a1.w};
#pragma unroll
            for (int b = 0; b < 8; b++) {
                acc[b][0] += ab[b] * u0; acc[b][1] += ab[b] * u1;
                acc[b][2] += ab[b] * u2; acc[b][3] += ab[b] * u3;
            }
        }
    }
    float* up = g_U + (size_t)d * 1024 + lane * 4;
#pragma unroll
    for (int b = 0; b < 8; b++)
        *(float4*)(up + b * 128) = make_float4(acc[b][0], acc[b][1], acc[b][2], acc[b][3]);
}

// ---------------- ugemm: msg[:, 16b:16b+16] = U[:, b, :] @ Wv[:, 16b:16b+16] ----------------
__global__ __launch_bounds__(256) void k_ugemm(const float* __restrict__ Wv) {
    extern __shared__ float sm[];
    float* sU = sm;            // 128 atoms x 128 dims (64 KB)
    float* sW = sm + 16384;    // 128 x 16 (8 KB)
    int b = blockIdx.y, n0 = blockIdx.x * 128, tid = threadIdx.x;

    for (int i = tid; i < 128 * 16; i += 256) {
        int k = i >> 4, c = i & 15;
        sW[i] = Wv[k * 128 + b * 16 + c];
    }
    for (int i = tid; i < 128 * 32; i += 256) {
        int r = i >> 5, kq = i & 31;
        int n = n0 + r;
        float4 v = (n < NA) ? *(const float4*)(g_U + (size_t)n * 1024 + b * 128 + kq * 4)
                            : make_float4(0.f, 0.f, 0.f, 0.f);
        *(float4*)(sU + r * 128 + kq * 4) = v;
    }
    __syncthreads();

    int col = tid & 15, rg = tid >> 4;   // rows rg*8..rg*8+7
    float acc[8] = {0.f, 0.f, 0.f, 0.f, 0.f, 0.f, 0.f, 0.f};
#pragma unroll 4
    for (int k4 = 0; k4 < 128; k4 += 4) {
        float bw[4];
#pragma unroll
        for (int q = 0; q < 4; q++) bw[q] = sW[(k4 + q) * 16 + col];
#pragma unroll
        for (int j = 0; j < 8; j++) {
            float4 av = *(const float4*)(sU + (rg * 8 + j) * 128 + k4);
            acc[j] += av.x * bw[0] + av.y * bw[1] + av.z * bw[2] + av.w * bw[3];
        }
    }
#pragma unroll
    for (int j = 0; j < 8; j++) {
        int n = n0 + rg * 8 + j;
        if (n < NA) g_msg[(size_t)n * 128 + b * 16 + col] = acc[j];
    }
}

// ---------------- final: x += msg @ Wo; reset counters for next call ----------------
__global__ __launch_bounds__(512) void k_out(float* __restrict__ x,
                                             const float* __restrict__ Wo) {
    extern __shared__ float sm[];
    float* sA  = sm;
    float* sBt = sA + 16384;
    int tid = threadIdx.x, lane = tid & 31, w = tid >> 5;
    int wm = w & 3, wn = w >> 2;
    int g = lane >> 2, t4 = lane & 3;
    int n0 = blockIdx.x * 128;

    int gidx = blockIdx.x * 512 + tid;
    if (gidx < NA) { g_cnt_all[gidx] = 0; g_cnt_live[gidx] = 0; }

    for (int i = tid; i < 128 * 128; i += 512) {
        int r = i >> 7, c = i & 127;
        int n = n0 + r;
        sA[fragA_idx<16>(r, c)] = (n < NA) ? f2tff(g_msg[(size_t)n * 128 + c]) : 0.f;
    }
    for (int i = tid; i < 128 * 128; i += 512) {
        int k = i >> 7, n = i & 127;
        sBt[fragB_idx<16>(k, n)] = f2tff(Wo[i]);
    }
    __syncthreads();

    float4 acc[2][4];
    zacc4(acc);
    mma_tile_frag<16>(sA, sBt, wm, wn, lane, acc);
#pragma unroll
    for (int mi = 0; mi < 2; mi++) {
        int r = 32 * wm + 16 * mi + g;
#pragma unroll
        for (int jl = 0; jl < 4; jl++) {
            int c = 32 * wn + 8 * jl + 2 * t4;
            float4 d = acc[mi][jl];
            int n1 = n0 + r, n2 = n1 + 8;
            if (n1 < NA) {
                float2 o = *(float2*)(x + (size_t)n1 * 128 + c);
                o.x += d.x; o.y += d.y;
                *(float2*)(x + (size_t)n1 * 128 + c) = o;
            }
            if (n2 < NA) {
                float2 o = *(float2*)(x + (size_t)n2 * 128 + c);
                o.x += d.z; o.y += d.w;
                *(float2*)(x + (size_t)n2 * 128 + c) = o;
            }
        }
    }
}

// ---------------- launch ----------------
extern "C" void kernel_launch(void* const* d_in, const int* in_sizes, int n_in,
                              void* d_out, int out_size) {
    const float* xyz = (const float*)d_in[0];
    const float* emb = (const float*)d_in[1];
    const float* te  = (const float*)d_in[2];
    const float* Wl  = (const float*)d_in[3];
    const float* bl  = (const float*)d_in[4];
    const float* W1f = (const float*)d_in[5];
    const float* b1f = (const float*)d_in[6];
    const float* W2f = (const float*)d_in[7];
    const float* b2f = (const float*)d_in[8];
    const float* Wq  = (const float*)d_in[9];
    const float* Wk  = (const float*)d_in[10];
    const float* Wv  = (const float*)d_in[11];
    const float* Wo  = (const float*)d_in[12];
    const int*   z   = (const int*)d_in[13];
    const int*   src = (const int*)d_in[14];
    const int*   dst = (const int*)d_in[15];
    float* x = (float*)d_out;

    const int SM_FILTER = (4096 + 16384 + 4096 + 4096 + 16384 + 4 * 128) * 4;
    const int SM_OQK    = (2 * 16384) * 4;
    const int SM_UGEMM  = (16384 + 128 * 16) * 4;   // 73728
    const int SM_OUT    = (2 * 16384) * 4;

    cudaFuncSetAttribute(k_filter, cudaFuncAttributeMaxDynamicSharedMemorySize, SM_FILTER);
    cudaFuncSetAttribute(k_oqk,    cudaFuncAttributeMaxDynamicSharedMemorySize, SM_OQK);
    cudaFuncSetAttribute(k_ugemm,  cudaFuncAttributeMaxDynamicSharedMemorySize, SM_UGEMM);
    cudaFuncSetAttribute(k_out,    cudaFuncAttributeMaxDynamicSharedMemorySize, SM_OUT);

    k_hist<<<NE / 256, 256>>>(xyz, src, dst);
    k_scan<<<1, 512>>>();
    k_scatter<<<NE / 256, 256>>>(xyz, src, dst);
    k_filter<<<NSM, 512, SM_FILTER>>>(xyz, Wl, bl, W1f, b1f, W2f, b2f);
    k_embed<<<(NA * DD + 255) / 256, 256>>>(emb, z, x);

    const int NBLK = (NA + 127) / 128;   // 157
    dim3 ug(NBLK, 8);
    for (int it = 0; it < NIT; it++) {
        k_oqk<<<NBLK, 512, SM_OQK>>>(x, te, Wo, Wq, Wk, it);
        k_attn<<<(NA * 32 + 255) / 256, 256>>>();
        k_ugemm<<<ug, 256, SM_UGEMM>>>(Wv);
    }
    k_out<<<NBLK, 512, SM_OUT>>>(x, Wo);
}